// round 3
// baseline (speedup 1.0000x reference)
#include <cuda_runtime.h>

// Problem constants
#define N_TOTAL   32768      // 8 * 16*16*16 rows of z_flat
#define K_CODES   8192
#define C_DIM     256
#define S_SPATIAL 4096       // 16*16*16
#define CS        (C_DIM * S_SPATIAL)

#define BN 128
#define BK 128
#define BC 8

// Output layout in d_out (float32, concatenated reference outputs):
//   [0, 8388608)            : out  [8,256,16,16,16]
//   [8388608]               : loss (scalar)
//   [8388609, 8421377)      : idx  [32768] (as float)
#define OUT_Z_ELEMS 8388608

// Scratch (static device globals - no allocation)
__device__ float g_znorm[N_TOTAL];
__device__ float g_cnorm[K_CODES];
__device__ int   g_idx[N_TOTAL];

__global__ void init_loss_kernel(float* loss) { *loss = 0.0f; }

// grid 320, block 128: blocks [0,256) compute znorm (128 rows each),
// blocks [256,320) compute cnorm (128 codes each, 1 thread per code).
__global__ void norms_kernel(const float* __restrict__ z,
                             const float* __restrict__ cb) {
    if (blockIdx.x < 256) {
        int n0 = blockIdx.x * 128;
        int b  = n0 >> 12;
        int s0 = n0 & 4095;
        const float* zr = z + (size_t)b * CS + s0 + threadIdx.x;
        float sum = 0.0f;
        #pragma unroll 8
        for (int c = 0; c < C_DIM; c++) {
            float v = zr[(size_t)c * S_SPATIAL];
            sum += v * v;
        }
        g_znorm[n0 + threadIdx.x] = sum;
    } else {
        int k = (blockIdx.x - 256) * 128 + threadIdx.x;
        const float4* cr = (const float4*)(cb + (size_t)k * C_DIM);
        float sum = 0.0f;
        #pragma unroll 8
        for (int i = 0; i < C_DIM / 4; i++) {
            float4 v = cr[i];
            sum += v.x * v.x + v.y * v.y + v.z * v.z + v.w * v.w;
        }
        g_cnorm[k] = sum;
    }
}

// Fused GEMM + argmin.
// grid = 256 CTAs (one per 128 rows), block = 256 threads.
// Each CTA loops over all 64 K-tiles of 128 codes, maintaining per-thread
// running (min score, index) for its 8 rows over its 8 columns per tile;
// cross-thread reduction at the end.
__global__ void __launch_bounds__(256)
argmin_kernel(const float* __restrict__ z,
              const float* __restrict__ cb,
              float* __restrict__ out_idx_f) {
    __shared__ float As[2][BC][132];
    __shared__ float Bs[2][BC][132];
    __shared__ float cns[BK];
    __shared__ float zns[BN];
    __shared__ float redS[BN][17];
    __shared__ int   redI[BN][17];

    int tid = threadIdx.x;
    int n0  = blockIdx.x * BN;
    int b   = n0 >> 12;
    int s0  = n0 & 4095;
    const float* zA = z + (size_t)b * CS + s0;   // + c*S_SPATIAL + s

    int tx = tid & 15;           // k dimension (8 cols each)
    int ty = tid >> 4;           // n dimension (8 rows each)
    int row0 = ty * 8;
    int col0 = tx * 8;

    // global load mappings
    int a_c = tid >> 5;          // 0..7  channel within chunk
    int a_s = (tid & 31) * 4;    // 0..124 spatial offset (float4)
    int b_k = tid >> 1;          // 0..127 code row
    int b_c = (tid & 1) * 4;     // 0 or 4 channel offset (float4)

    if (tid < BN) zns[tid] = g_znorm[n0 + tid];

    float best[8];
    int   bidx[8];
    #pragma unroll
    for (int i = 0; i < 8; i++) { best[i] = 3.4e38f; bidx[i] = 0; }

    for (int kt = 0; kt < K_CODES / BK; kt++) {
        int k0 = kt * BK;
        __syncthreads();   // protect smem reuse across tiles
        if (tid < BK) cns[tid] = g_cnorm[k0 + tid];

        // prologue: chunk 0 -> buffer 0
        float4 ra = *(const float4*)(zA + (size_t)a_c * S_SPATIAL + a_s);
        float4 rb = *(const float4*)(cb + (size_t)(k0 + b_k) * C_DIM + b_c);
        *(float4*)&As[0][a_c][a_s] = ra;
        Bs[0][b_c + 0][b_k] = rb.x;
        Bs[0][b_c + 1][b_k] = rb.y;
        Bs[0][b_c + 2][b_k] = rb.z;
        Bs[0][b_c + 3][b_k] = rb.w;
        __syncthreads();

        float acc[8][8] = {};
        int buf = 0;
        for (int cc = 0; cc < C_DIM; cc += BC) {
            int nc = cc + BC;
            float4 na, nb;
            if (nc < C_DIM) {
                na = *(const float4*)(zA + (size_t)(nc + a_c) * S_SPATIAL + a_s);
                nb = *(const float4*)(cb + (size_t)(k0 + b_k) * C_DIM + nc + b_c);
            }
            #pragma unroll
            for (int c = 0; c < BC; c++) {
                float a[8], bb[8];
                *(float4*)&a[0]  = *(float4*)&As[buf][c][row0];
                *(float4*)&a[4]  = *(float4*)&As[buf][c][row0 + 4];
                *(float4*)&bb[0] = *(float4*)&Bs[buf][c][col0];
                *(float4*)&bb[4] = *(float4*)&Bs[buf][c][col0 + 4];
                #pragma unroll
                for (int i = 0; i < 8; i++)
                    #pragma unroll
                    for (int j = 0; j < 8; j++)
                        acc[i][j] = fmaf(a[i], bb[j], acc[i][j]);
            }
            if (nc < C_DIM) {
                buf ^= 1;
                *(float4*)&As[buf][a_c][a_s] = na;
                Bs[buf][b_c + 0][b_k] = nb.x;
                Bs[buf][b_c + 1][b_k] = nb.y;
                Bs[buf][b_c + 2][b_k] = nb.z;
                Bs[buf][b_c + 3][b_k] = nb.w;
                __syncthreads();
            }
        }

        // epilogue: score = fl(fl(zn + cn) - 2*dot), mimic reference rounding
        #pragma unroll
        for (int i = 0; i < 8; i++) {
            float zni = zns[row0 + i];
            #pragma unroll
            for (int j = 0; j < 8; j++) {
                float s = __fadd_rn(__fadd_rn(zni, cns[col0 + j]),
                                    -2.0f * acc[i][j]);
                if (s < best[i]) {        // strict <  => first (lowest) index wins
                    best[i] = s;
                    bidx[i] = k0 + col0 + j;
                }
            }
        }
    }

    // cross-thread reduction: 16 tx-groups share each row
    __syncthreads();
    #pragma unroll
    for (int i = 0; i < 8; i++) {
        redS[row0 + i][tx] = best[i];
        redI[row0 + i][tx] = bidx[i];
    }
    __syncthreads();
    if (tid < BN) {
        float bs = redS[tid][0];
        int   bk = redI[tid][0];
        #pragma unroll
        for (int t = 1; t < 16; t++) {
            float s  = redS[tid][t];
            int   k2 = redI[tid][t];
            if (s < bs || (s == bs && k2 < bk)) { bs = s; bk = k2; }
        }
        g_idx[n0 + tid]     = bk;
        out_idx_f[n0 + tid] = (float)bk;
    }
}

// Gather z_q, write straight-through output (zp + (z_q - zp)), accumulate loss.
// grid 128, block 256: one thread per row n, loop over channels.
__global__ void gather_loss_kernel(const float* __restrict__ z,
                                   const float* __restrict__ cb,
                                   float* __restrict__ out,
                                   float* __restrict__ loss) {
    int tid = threadIdx.x;
    int n = blockIdx.x * 256 + tid;
    int b = n >> 12;
    int s = n & 4095;
    int ci = g_idx[n];
    const float*  zr   = z   + (size_t)b * CS + s;
    float*        orow = out + (size_t)b * CS + s;
    const float4* cr   = (const float4*)(cb + (size_t)ci * C_DIM);

    float sum = 0.0f;
    #pragma unroll 4
    for (int c4 = 0; c4 < C_DIM / 4; c4++) {
        float4 q = cr[c4];
        size_t base = (size_t)(c4 * 4) * S_SPATIAL;
        float z0 = zr[base];
        float z1 = zr[base + S_SPATIAL];
        float z2 = zr[base + 2 * S_SPATIAL];
        float z3 = zr[base + 3 * S_SPATIAL];
        // d = fl(z_q - zp); out = fl(zp + d)  (matches straight-through estimator)
        float d0 = __fadd_rn(q.x, -z0);
        float d1 = __fadd_rn(q.y, -z1);
        float d2 = __fadd_rn(q.z, -z2);
        float d3 = __fadd_rn(q.w, -z3);
        orow[base]                 = __fadd_rn(z0, d0);
        orow[base + S_SPATIAL]     = __fadd_rn(z1, d1);
        orow[base + 2 * S_SPATIAL] = __fadd_rn(z2, d2);
        orow[base + 3 * S_SPATIAL] = __fadd_rn(z3, d3);
        sum += d0 * d0 + d1 * d1 + d2 * d2 + d3 * d3;
    }

    // block reduction
    __shared__ float wsum[8];
    #pragma unroll
    for (int off = 16; off > 0; off >>= 1)
        sum += __shfl_down_sync(0xffffffffu, sum, off);
    if ((tid & 31) == 0) wsum[tid >> 5] = sum;
    __syncthreads();
    if (tid == 0) {
        float t = 0.0f;
        #pragma unroll
        for (int w = 0; w < 8; w++) t += wsum[w];
        // loss = mean((zq-zp)^2) + BETA*mean(...) = 2 * sum / (N*C)
        atomicAdd(loss, t * (2.0f / (float)(N_TOTAL * C_DIM)));
    }
}

extern "C" void kernel_launch(void* const* d_in, const int* in_sizes, int n_in,
                              void* d_out, int out_size) {
    (void)in_sizes; (void)n_in; (void)out_size;
    const float* z  = (const float*)d_in[0];
    const float* cb = (const float*)d_in[1];
    float* out  = (float*)d_out;
    float* loss = out + OUT_Z_ELEMS;
    float* idxf = out + OUT_Z_ELEMS + 1;

    init_loss_kernel<<<1, 1>>>(loss);
    norms_kernel<<<320, 128>>>(z, cb);
    argmin_kernel<<<256, 256>>>(z, cb, idxf);
    gather_loss_kernel<<<128, 256>>>(z, cb, out, loss);
}

// round 4
// speedup vs baseline: 1.0651x; 1.0651x over previous
#include <cuda_runtime.h>

// Problem constants
#define N_TOTAL   32768      // 8 * 16*16*16 rows of z_flat
#define K_CODES   8192
#define C_DIM     256
#define S_SPATIAL 4096       // 16*16*16
#define CS        (C_DIM * S_SPATIAL)

#define BN 128
#define BK 128
#define BC 8

// Output layout in d_out (float32, concatenated reference outputs):
//   [0, 8388608)            : out  [8,256,16,16,16]
//   [8388608]               : loss (scalar)
//   [8388609, 8421377)      : idx  [32768] (as float)
#define OUT_Z_ELEMS 8388608

// Scratch (static device globals - no allocation)
__device__ float g_znorm[N_TOTAL];
__device__ float g_cnorm[K_CODES];
__device__ int   g_idx[N_TOTAL];

// Packed dual-fp32 FMA (Blackwell f32x2 pipe). Each lane is an independent
// fma.rn — bit-identical to two scalar fmaf's.
__device__ __forceinline__ unsigned long long fma2(unsigned long long a,
                                                   unsigned long long b,
                                                   unsigned long long c) {
    unsigned long long d;
    asm("fma.rn.f32x2 %0, %1, %2, %3;" : "=l"(d) : "l"(a), "l"(b), "l"(c));
    return d;
}
__device__ __forceinline__ unsigned long long dup2(float x) {
    unsigned long long d;
    asm("mov.b64 %0, {%1, %1};" : "=l"(d) : "r"(__float_as_uint(x)));
    return d;
}
__device__ __forceinline__ float lo32(unsigned long long v) {
    return __uint_as_float((unsigned)v);
}
__device__ __forceinline__ float hi32(unsigned long long v) {
    return __uint_as_float((unsigned)(v >> 32));
}

__global__ void init_loss_kernel(float* loss) { *loss = 0.0f; }

// grid 320, block 128: blocks [0,256) compute znorm (128 rows each),
// blocks [256,320) compute cnorm (128 codes each, 1 thread per code).
__global__ void norms_kernel(const float* __restrict__ z,
                             const float* __restrict__ cb) {
    if (blockIdx.x < 256) {
        int n0 = blockIdx.x * 128;
        int b  = n0 >> 12;
        int s0 = n0 & 4095;
        const float* zr = z + (size_t)b * CS + s0 + threadIdx.x;
        float sum = 0.0f;
        #pragma unroll 8
        for (int c = 0; c < C_DIM; c++) {
            float v = zr[(size_t)c * S_SPATIAL];
            sum += v * v;
        }
        g_znorm[n0 + threadIdx.x] = sum;
    } else {
        int k = (blockIdx.x - 256) * 128 + threadIdx.x;
        const float4* cr = (const float4*)(cb + (size_t)k * C_DIM);
        float sum = 0.0f;
        #pragma unroll 8
        for (int i = 0; i < C_DIM / 4; i++) {
            float4 v = cr[i];
            sum += v.x * v.x + v.y * v.y + v.z * v.z + v.w * v.w;
        }
        g_cnorm[k] = sum;
    }
}

// Fused GEMM + argmin with packed f32x2 FMAs.
// grid = 256 CTAs (one per 128 rows), block = 256 threads.
// Per-thread 8 rows x 8 cols fragment; cols held as 4 packed f32x2 pairs.
__global__ void __launch_bounds__(256)
argmin_kernel(const float* __restrict__ z,
              const float* __restrict__ cb,
              float* __restrict__ out_idx_f) {
    __shared__ float As[2][BC][132];
    __shared__ float Bs[2][BC][132];
    __shared__ float cns[BK];
    __shared__ float zns[BN];
    __shared__ float redS[BN][17];
    __shared__ int   redI[BN][17];

    int tid = threadIdx.x;
    int n0  = blockIdx.x * BN;
    int b   = n0 >> 12;
    int s0  = n0 & 4095;
    const float* zA = z + (size_t)b * CS + s0;   // + c*S_SPATIAL + s

    int tx = tid & 15;           // k dimension (8 cols each)
    int ty = tid >> 4;           // n dimension (8 rows each)
    int row0 = ty * 8;
    int col0 = tx * 8;

    // global load mappings
    int a_c = tid >> 5;          // 0..7  channel within chunk
    int a_s = (tid & 31) * 4;    // 0..124 spatial offset (float4)
    int b_k = tid >> 1;          // 0..127 code row
    int b_c = (tid & 1) * 4;     // 0 or 4 channel offset (float4)

    if (tid < BN) zns[tid] = g_znorm[n0 + tid];

    float best[8];
    int   bidx[8];
    #pragma unroll
    for (int i = 0; i < 8; i++) { best[i] = 3.4e38f; bidx[i] = 0; }

    for (int kt = 0; kt < K_CODES / BK; kt++) {
        int k0 = kt * BK;
        __syncthreads();   // protect smem reuse across tiles
        if (tid < BK) cns[tid] = g_cnorm[k0 + tid];

        // prologue: chunk 0 -> buffer 0
        float4 ra = *(const float4*)(zA + (size_t)a_c * S_SPATIAL + a_s);
        float4 rb = *(const float4*)(cb + (size_t)(k0 + b_k) * C_DIM + b_c);
        *(float4*)&As[0][a_c][a_s] = ra;
        Bs[0][b_c + 0][b_k] = rb.x;
        Bs[0][b_c + 1][b_k] = rb.y;
        Bs[0][b_c + 2][b_k] = rb.z;
        Bs[0][b_c + 3][b_k] = rb.w;
        __syncthreads();

        unsigned long long acc2[8][4] = {};   // packed (col 2j, col 2j+1)
        int buf = 0;
        for (int cc = 0; cc < C_DIM; cc += BC) {
            int nc = cc + BC;
            float4 na, nb;
            if (nc < C_DIM) {
                na = *(const float4*)(zA + (size_t)(nc + a_c) * S_SPATIAL + a_s);
                nb = *(const float4*)(cb + (size_t)(k0 + b_k) * C_DIM + nc + b_c);
            }
            #pragma unroll
            for (int c = 0; c < BC; c++) {
                float a[8];
                *(float4*)&a[0] = *(float4*)&As[buf][c][row0];
                *(float4*)&a[4] = *(float4*)&As[buf][c][row0 + 4];
                // B pairs read directly as 64-bit packed values (32B aligned)
                ulonglong2 bA = *(const ulonglong2*)&Bs[buf][c][col0];
                ulonglong2 bB = *(const ulonglong2*)&Bs[buf][c][col0 + 4];
                unsigned long long b2[4] = {bA.x, bA.y, bB.x, bB.y};
                #pragma unroll
                for (int i = 0; i < 8; i++) {
                    unsigned long long ad = dup2(a[i]);
                    #pragma unroll
                    for (int j2 = 0; j2 < 4; j2++)
                        acc2[i][j2] = fma2(ad, b2[j2], acc2[i][j2]);
                }
            }
            if (nc < C_DIM) {
                buf ^= 1;
                *(float4*)&As[buf][a_c][a_s] = na;
                Bs[buf][b_c + 0][b_k] = nb.x;
                Bs[buf][b_c + 1][b_k] = nb.y;
                Bs[buf][b_c + 2][b_k] = nb.z;
                Bs[buf][b_c + 3][b_k] = nb.w;
                __syncthreads();
            }
        }

        // epilogue: score = fl(fl(zn + cn) - 2*dot), mimic reference rounding
        #pragma unroll
        for (int i = 0; i < 8; i++) {
            float zni = zns[row0 + i];
            #pragma unroll
            for (int j2 = 0; j2 < 4; j2++) {
                float dlo = lo32(acc2[i][j2]);
                float dhi = hi32(acc2[i][j2]);
                float slo = __fadd_rn(__fadd_rn(zni, cns[col0 + 2 * j2]),
                                      -2.0f * dlo);
                float shi = __fadd_rn(__fadd_rn(zni, cns[col0 + 2 * j2 + 1]),
                                      -2.0f * dhi);
                if (slo < best[i]) {      // strict < => lowest index wins
                    best[i] = slo;
                    bidx[i] = k0 + col0 + 2 * j2;
                }
                if (shi < best[i]) {
                    best[i] = shi;
                    bidx[i] = k0 + col0 + 2 * j2 + 1;
                }
            }
        }
    }

    // cross-thread reduction: 16 tx-groups share each row
    __syncthreads();
    #pragma unroll
    for (int i = 0; i < 8; i++) {
        redS[row0 + i][tx] = best[i];
        redI[row0 + i][tx] = bidx[i];
    }
    __syncthreads();
    if (tid < BN) {
        float bs = redS[tid][0];
        int   bk = redI[tid][0];
        #pragma unroll
        for (int t = 1; t < 16; t++) {
            float s  = redS[tid][t];
            int   k2 = redI[tid][t];
            if (s < bs || (s == bs && k2 < bk)) { bs = s; bk = k2; }
        }
        g_idx[n0 + tid]     = bk;
        out_idx_f[n0 + tid] = (float)bk;
    }
}

// Gather z_q, write straight-through output (zp + (z_q - zp)), accumulate loss.
// grid 128, block 256: one thread per row n, loop over channels.
__global__ void gather_loss_kernel(const float* __restrict__ z,
                                   const float* __restrict__ cb,
                                   float* __restrict__ out,
                                   float* __restrict__ loss) {
    int tid = threadIdx.x;
    int n = blockIdx.x * 256 + tid;
    int b = n >> 12;
    int s = n & 4095;
    int ci = g_idx[n];
    const float*  zr   = z   + (size_t)b * CS + s;
    float*        orow = out + (size_t)b * CS + s;
    const float4* cr   = (const float4*)(cb + (size_t)ci * C_DIM);

    float sum = 0.0f;
    #pragma unroll 4
    for (int c4 = 0; c4 < C_DIM / 4; c4++) {
        float4 q = cr[c4];
        size_t base = (size_t)(c4 * 4) * S_SPATIAL;
        float z0 = zr[base];
        float z1 = zr[base + S_SPATIAL];
        float z2 = zr[base + 2 * S_SPATIAL];
        float z3 = zr[base + 3 * S_SPATIAL];
        // d = fl(z_q - zp); out = fl(zp + d)  (matches straight-through estimator)
        float d0 = __fadd_rn(q.x, -z0);
        float d1 = __fadd_rn(q.y, -z1);
        float d2 = __fadd_rn(q.z, -z2);
        float d3 = __fadd_rn(q.w, -z3);
        orow[base]                 = __fadd_rn(z0, d0);
        orow[base + S_SPATIAL]     = __fadd_rn(z1, d1);
        orow[base + 2 * S_SPATIAL] = __fadd_rn(z2, d2);
        orow[base + 3 * S_SPATIAL] = __fadd_rn(z3, d3);
        sum += d0 * d0 + d1 * d1 + d2 * d2 + d3 * d3;
    }

    // block reduction
    __shared__ float wsum[8];
    #pragma unroll
    for (int off = 16; off > 0; off >>= 1)
        sum += __shfl_down_sync(0xffffffffu, sum, off);
    if ((tid & 31) == 0) wsum[tid >> 5] = sum;
    __syncthreads();
    if (tid == 0) {
        float t = 0.0f;
        #pragma unroll
        for (int w = 0; w < 8; w++) t += wsum[w];
        // loss = mean((zq-zp)^2) + BETA*mean(...) = 2 * sum / (N*C)
        atomicAdd(loss, t * (2.0f / (float)(N_TOTAL * C_DIM)));
    }
}

extern "C" void kernel_launch(void* const* d_in, const int* in_sizes, int n_in,
                              void* d_out, int out_size) {
    (void)in_sizes; (void)n_in; (void)out_size;
    const float* z  = (const float*)d_in[0];
    const float* cb = (const float*)d_in[1];
    float* out  = (float*)d_out;
    float* loss = out + OUT_Z_ELEMS;
    float* idxf = out + OUT_Z_ELEMS + 1;

    init_loss_kernel<<<1, 1>>>(loss);
    norms_kernel<<<320, 128>>>(z, cb);
    argmin_kernel<<<256, 256>>>(z, cb, idxf);
    gather_loss_kernel<<<128, 256>>>(z, cb, out, loss);
}